// round 1
// baseline (speedup 1.0000x reference)
#include <cuda_runtime.h>

// ---------------------------------------------------------------------------
// EnrichClassifier: block-sparse pathway MLP.
//   dims: x[8192,5000] -> h1[4000] -> h2[2000] -> h3[1000] -> scores[200] -> out[50]
//   Regular structure: every pathway has exactly 100 genes, l1=20, l2=10, l3=5.
//   Layers 2..4 are block-diagonal; only m1 (200 rows of it) must be read.
// ---------------------------------------------------------------------------

#define NG   5000   // genes
#define NB   8192   // batch
#define NP   200    // pathways
#define NKG  100    // genes per pathway
#define NL1  20     // layer-1 units per pathway
#define NL2  10
#define NL3  5
#define NH1  4000
#define NH2  2000
#define NH3  1000
#define NLBL 50

// ---- scratch (device globals: only allowed form of scratch) ----------------
__device__ __align__(16) float g_xT[(size_t)NG * NB];            // 163.84 MB transposed x
__device__ int   g_geneoff[NP * NKG];                            // gene * NB element offsets
__device__ __align__(16) float g_w1f[NP * NKG * NL1 * 2];        // BN-folded, duplicated pairs [p][s][j][2]
__device__ float g_b1f[NP * NL1];
__device__ __align__(16) float g_w2f[NP * NL1 * NL2 * 2];        // [p][t][j][2]
__device__ float g_b2f[NP * NL2];
__device__ __align__(16) float g_w3f[NP * NL2 * NL3 * 2];        // [p][t][j][2]
__device__ float g_b3f[NP * NL3];
__device__ __align__(16) float g_w4f[NP * NL3 * 2];              // [p][t][2]
__device__ __align__(16) float g_scoresT[(size_t)NP * NB];       // [p][b]

// ---- packed f32x2 helpers ---------------------------------------------------
__device__ __forceinline__ unsigned long long fma2(unsigned long long a,
                                                   unsigned long long b,
                                                   unsigned long long c) {
    unsigned long long d;
    asm("fma.rn.f32x2 %0, %1, %2, %3;" : "=l"(d) : "l"(a), "l"(b), "l"(c));
    return d;
}

__device__ __forceinline__ unsigned long long bias_relu2(unsigned long long v, float bias) {
    float a, b;
    asm("mov.b64 {%0, %1}, %2;" : "=f"(a), "=f"(b) : "l"(v));
    a = fmaxf(a + bias, 0.0f);
    b = fmaxf(b + bias, 0.0f);
    unsigned long long r;
    asm("mov.b64 %0, {%1, %2};" : "=l"(r) : "f"(a), "f"(b));
    return r;
}

// ---------------------------------------------------------------------------
// K1: extract the 100 gene indices of each pathway from m1 row p*NL1.
// Deterministic compaction (per-thread count + serial exclusive scan).
// ---------------------------------------------------------------------------
__global__ void extract_genes_kernel(const float* __restrict__ m1) {
    const int p = blockIdx.x;
    const int tid = threadIdx.x;                 // 256 threads
    const float* row = m1 + (size_t)(p * NL1) * NG;

    __shared__ int cnt[257];
    const int CH = (NG + 255) / 256;             // 20
    int start = tid * CH;
    int end = start + CH; if (end > NG) end = NG;
    if (start > NG) start = NG;

    int c = 0;
    for (int g = start; g < end; g++) c += (row[g] != 0.0f);
    cnt[tid + 1] = c;
    __syncthreads();
    if (tid == 0) {
        cnt[0] = 0;
        for (int i = 1; i <= 256; i++) cnt[i] += cnt[i - 1];
    }
    __syncthreads();
    int off = cnt[tid];
    for (int g = start; g < end; g++) {
        if (row[g] != 0.0f) g_geneoff[p * NKG + off++] = g * NB;
    }
}

// ---------------------------------------------------------------------------
// K2: gather w1 along genes, fold eval-mode BatchNorm (scale into W, shift
// into bias) for layers 1..3, store all weights as duplicated f32 pairs.
// ---------------------------------------------------------------------------
__global__ void fold_weights_kernel(
    const float* __restrict__ w1, const float* __restrict__ b1,
    const float* __restrict__ w2, const float* __restrict__ b2,
    const float* __restrict__ w3, const float* __restrict__ b3,
    const float* __restrict__ w4,
    const float* __restrict__ ga1, const float* __restrict__ be1,
    const float* __restrict__ rm1, const float* __restrict__ rv1,
    const float* __restrict__ ga2, const float* __restrict__ be2,
    const float* __restrict__ rm2, const float* __restrict__ rv2,
    const float* __restrict__ ga3, const float* __restrict__ be3,
    const float* __restrict__ rm3, const float* __restrict__ rv3) {
    const int p = blockIdx.x;
    const int tid = threadIdx.x;                 // 128 threads

    __shared__ float s1[NL1], s2[NL2], s3[NL3];
    if (tid < NL1) {
        int u = p * NL1 + tid;
        float s = ga1[u] * rsqrtf(rv1[u] + 1e-5f);
        s1[tid] = s;
        g_b1f[u] = s * (b1[u] - rm1[u]) + be1[u];
    }
    if (tid < NL2) {
        int u = p * NL2 + tid;
        float s = ga2[u] * rsqrtf(rv2[u] + 1e-5f);
        s2[tid] = s;
        g_b2f[u] = s * (b2[u] - rm2[u]) + be2[u];
    }
    if (tid < NL3) {
        int u = p * NL3 + tid;
        float s = ga3[u] * rsqrtf(rv3[u] + 1e-5f);
        s3[tid] = s;
        g_b3f[u] = s * (b3[u] - rm3[u]) + be3[u];
    }
    __syncthreads();

    // layer-1 gather + fold: [p][s][j] duplicated pairs
    for (int i = tid; i < NKG * NL1; i += 128) {
        int s = i / NL1, j = i - s * NL1;
        int gene = g_geneoff[p * NKG + s] >> 13;          // / NB
        float v = w1[(size_t)(p * NL1 + j) * NG + gene] * s1[j];
        size_t o = (((size_t)p * NKG + s) * NL1 + j) * 2;
        g_w1f[o] = v; g_w1f[o + 1] = v;
    }
    // layer-2 block (contiguous columns) : [p][t][j]
    for (int i = tid; i < NL1 * NL2; i += 128) {
        int t = i / NL2, j = i - t * NL2;
        float v = w2[(size_t)(p * NL2 + j) * NH1 + p * NL1 + t] * s2[j];
        size_t o = (((size_t)p * NL1 + t) * NL2 + j) * 2;
        g_w2f[o] = v; g_w2f[o + 1] = v;
    }
    // layer-3 block : [p][t][j]
    for (int i = tid; i < NL2 * NL3; i += 128) {
        int t = i / NL3, j = i - t * NL3;
        float v = w3[(size_t)(p * NL3 + j) * NH2 + p * NL2 + t] * s3[j];
        size_t o = (((size_t)p * NL2 + t) * NL3 + j) * 2;
        g_w3f[o] = v; g_w3f[o + 1] = v;
    }
    // layer-4 row (no BN) : [p][t]
    if (tid < NL3) {
        float v = w4[(size_t)p * NH3 + p * NL3 + tid];
        g_w4f[(p * NL3 + tid) * 2] = v;
        g_w4f[(p * NL3 + tid) * 2 + 1] = v;
    }
}

// ---------------------------------------------------------------------------
// K3: tiled transpose x[NB,NG] -> g_xT[NG,NB] (coalesced gene rows).
// ---------------------------------------------------------------------------
__global__ void transpose_kernel(const float* __restrict__ x) {
    __shared__ float tile[32][33];
    const int gx = blockIdx.x * 32;              // gene dim
    const int by = blockIdx.y * 32;              // batch dim
    const int tx = threadIdx.x, ty = threadIdx.y;   // (32, 8)

    #pragma unroll
    for (int r = 0; r < 32; r += 8) {
        int b = by + ty + r, g = gx + tx;
        tile[ty + r][tx] = (g < NG) ? x[(size_t)b * NG + g] : 0.0f;
    }
    __syncthreads();
    #pragma unroll
    for (int r = 0; r < 32; r += 8) {
        int g = gx + ty + r, b = by + tx;
        if (g < NG) g_xT[(size_t)g * NB + b] = tile[tx][ty + r];
    }
}

// ---------------------------------------------------------------------------
// K4: fused pathway chain. Grid (NP pathways fast, 32 batch tiles).
// 128 threads, each owns 2 consecutive batch rows packed as f32x2.
// All weights broadcast from smem; layer1 inner loop:
//   1 LDG.64 (x pair) + 10 LDS.128 (dup weight pairs) + 20 fma.rn.f32x2
// -> FFMA-pipe bound at full fp32 rate.
// ---------------------------------------------------------------------------
__global__ void __launch_bounds__(128) pathway_kernel(const float* __restrict__ b4) {
    const int p = blockIdx.x;
    const int tid = threadIdx.x;
    const int b0 = blockIdx.y * 256 + tid * 2;

    __shared__ ulonglong2 s_w1[NKG * NL1 / 2];           // [s][jj] 16 KB
    __shared__ unsigned long long s_w2[NL1 * NL2];       // [t][j]
    __shared__ unsigned long long s_w3[NL2 * NL3];       // [t][j]
    __shared__ unsigned long long s_w4[NL3];
    __shared__ int s_go[NKG];
    __shared__ float s_b1[NL1], s_b2[NL2], s_b3[NL3], s_b4;

    {
        const float4* src1 = reinterpret_cast<const float4*>(g_w1f + (size_t)p * NKG * NL1 * 2);
        float4* dst1 = reinterpret_cast<float4*>(s_w1);
        for (int i = tid; i < NKG * NL1 * 2 / 4; i += 128) dst1[i] = src1[i];

        const float2* src2 = reinterpret_cast<const float2*>(g_w2f + (size_t)p * NL1 * NL2 * 2);
        float2* dst2 = reinterpret_cast<float2*>(s_w2);
        for (int i = tid; i < NL1 * NL2; i += 128) dst2[i] = src2[i];

        const float2* src3 = reinterpret_cast<const float2*>(g_w3f + (size_t)p * NL2 * NL3 * 2);
        float2* dst3 = reinterpret_cast<float2*>(s_w3);
        if (tid < NL2 * NL3) dst3[tid] = src3[tid];

        const float2* src4 = reinterpret_cast<const float2*>(g_w4f + (size_t)p * NL3 * 2);
        float2* dst4 = reinterpret_cast<float2*>(s_w4);
        if (tid < NL3) dst4[tid] = src4[tid];

        if (tid < NKG) s_go[tid] = g_geneoff[p * NKG + tid];
        if (tid < NL1) s_b1[tid] = g_b1f[p * NL1 + tid];
        if (tid < NL2) s_b2[tid] = g_b2f[p * NL2 + tid];
        if (tid < NL3) s_b3[tid] = g_b3f[p * NL3 + tid];
        if (tid == 0)  s_b4 = b4[p];
    }
    __syncthreads();

    // ---- layer 1: 20 units x 100 genes ----
    unsigned long long h1[NL1];
    #pragma unroll
    for (int j = 0; j < NL1; j++) h1[j] = 0ULL;

    const float* xb = g_xT + b0;
    #pragma unroll 2
    for (int s = 0; s < NKG; s++) {
        unsigned long long xv =
            *reinterpret_cast<const unsigned long long*>(xb + s_go[s]);
        const ulonglong2* wr = s_w1 + s * (NL1 / 2);
        #pragma unroll
        for (int jj = 0; jj < NL1 / 2; jj++) {
            ulonglong2 w = wr[jj];
            h1[2 * jj]     = fma2(xv, w.x, h1[2 * jj]);
            h1[2 * jj + 1] = fma2(xv, w.y, h1[2 * jj + 1]);
        }
    }
    #pragma unroll
    for (int j = 0; j < NL1; j++) h1[j] = bias_relu2(h1[j], s_b1[j]);

    // ---- layer 2: 10 x 20 ----
    unsigned long long h2[NL2];
    #pragma unroll
    for (int j = 0; j < NL2; j++) h2[j] = 0ULL;
    #pragma unroll
    for (int t = 0; t < NL1; t++) {
        #pragma unroll
        for (int j = 0; j < NL2; j++)
            h2[j] = fma2(h1[t], s_w2[t * NL2 + j], h2[j]);
    }
    #pragma unroll
    for (int j = 0; j < NL2; j++) h2[j] = bias_relu2(h2[j], s_b2[j]);

    // ---- layer 3: 5 x 10 ----
    unsigned long long h3[NL3];
    #pragma unroll
    for (int j = 0; j < NL3; j++) h3[j] = 0ULL;
    #pragma unroll
    for (int t = 0; t < NL2; t++) {
        #pragma unroll
        for (int j = 0; j < NL3; j++)
            h3[j] = fma2(h2[t], s_w3[t * NL3 + j], h3[j]);
    }
    #pragma unroll
    for (int j = 0; j < NL3; j++) h3[j] = bias_relu2(h3[j], s_b3[j]);

    // ---- layer 4: pathway score ----
    unsigned long long sc = 0ULL;
    #pragma unroll
    for (int t = 0; t < NL3; t++) sc = fma2(h3[t], s_w4[t], sc);

    float sa, sb;
    asm("mov.b64 {%0, %1}, %2;" : "=f"(sa), "=f"(sb) : "l"(sc));
    sa = fmaxf(sa + s_b4, 0.0f);
    sb = fmaxf(sb + s_b4, 0.0f);
    *reinterpret_cast<float2*>(g_scoresT + (size_t)p * NB + b0) = make_float2(sa, sb);
}

// ---------------------------------------------------------------------------
// K5: classifier: out[b,l] = sum_k scoresT[k][b] * wc[l,k] + bc[l]
// ---------------------------------------------------------------------------
__global__ void __launch_bounds__(256) classifier_kernel(
    const float* __restrict__ wc, const float* __restrict__ bc,
    float* __restrict__ out) {
    __shared__ float s_wc[NLBL * NP];            // 40 KB
    __shared__ float s_bc[NLBL];
    const int tid = threadIdx.x;

    for (int i = tid; i < NLBL * NP; i += 256) s_wc[i] = wc[i];
    if (tid < NLBL) s_bc[tid] = bc[tid];
    __syncthreads();

    const int b = blockIdx.x * 256 + tid;
    float acc[NLBL];
    #pragma unroll
    for (int l = 0; l < NLBL; l++) acc[l] = s_bc[l];

    for (int k = 0; k < NP; k++) {
        float sv = g_scoresT[(size_t)k * NB + b];   // coalesced
        #pragma unroll
        for (int l = 0; l < NLBL; l++) acc[l] += sv * s_wc[l * NP + k];
    }
    float* o = out + (size_t)b * NLBL;
    #pragma unroll
    for (int l = 0; l < NLBL; l++) o[l] = acc[l];
}

// ---------------------------------------------------------------------------
// launch
// ---------------------------------------------------------------------------
extern "C" void kernel_launch(void* const* d_in, const int* in_sizes, int n_in,
                              void* d_out, int out_size) {
    const float* x   = (const float*)d_in[0];
    const float* w1  = (const float*)d_in[1];
    const float* b1  = (const float*)d_in[2];
    const float* m1  = (const float*)d_in[3];
    const float* w2  = (const float*)d_in[4];
    const float* b2  = (const float*)d_in[5];
    // m2 = d_in[6]  (unused: block-diagonal by construction)
    const float* w3  = (const float*)d_in[7];
    const float* b3  = (const float*)d_in[8];
    // m3 = d_in[9]
    const float* w4  = (const float*)d_in[10];
    const float* b4  = (const float*)d_in[11];
    // m4 = d_in[12]
    const float* ga1 = (const float*)d_in[13];
    const float* be1 = (const float*)d_in[14];
    const float* rm1 = (const float*)d_in[15];
    const float* rv1 = (const float*)d_in[16];
    const float* ga2 = (const float*)d_in[17];
    const float* be2 = (const float*)d_in[18];
    const float* rm2 = (const float*)d_in[19];
    const float* rv2 = (const float*)d_in[20];
    const float* ga3 = (const float*)d_in[21];
    const float* be3 = (const float*)d_in[22];
    const float* rm3 = (const float*)d_in[23];
    const float* rv3 = (const float*)d_in[24];
    const float* wc  = (const float*)d_in[25];
    const float* bc  = (const float*)d_in[26];
    float* out = (float*)d_out;

    extract_genes_kernel<<<NP, 256>>>(m1);
    fold_weights_kernel<<<NP, 128>>>(w1, b1, w2, b2, w3, b3, w4,
                                     ga1, be1, rm1, rv1,
                                     ga2, be2, rm2, rv2,
                                     ga3, be3, rm3, rv3);
    transpose_kernel<<<dim3((NG + 31) / 32, NB / 32), dim3(32, 8)>>>(x);
    pathway_kernel<<<dim3(NP, NB / 256), 128>>>(b4);
    classifier_kernel<<<NB / 256, 256>>>(wc, bc, out);
}

// round 3
// speedup vs baseline: 1.0155x; 1.0155x over previous
#include <cuda_runtime.h>

// ---------------------------------------------------------------------------
// EnrichClassifier: block-sparse pathway MLP.
//   dims: x[8192,5000] -> h1[4000] -> h2[2000] -> h3[1000] -> scores[200] -> out[50]
//   Regular structure: every pathway has exactly 100 genes, l1=20, l2=10, l3=5.
//   Layers 2..4 are block-diagonal; only m1 (200 rows of it) must be read.
// ---------------------------------------------------------------------------

#define NG   5000   // genes
#define NB   8192   // batch
#define NP   200    // pathways
#define NKG  100    // genes per pathway
#define NL1  20     // layer-1 units per pathway
#define NL2  10
#define NL3  5
#define NH1  4000
#define NH2  2000
#define NH3  1000
#define NLBL 50

// ---- scratch (device globals: only allowed form of scratch) ----------------
__device__ __align__(16) float g_xT[(size_t)NG * NB];            // 163.84 MB transposed x
__device__ int   g_geneoff[NP * NKG];                            // gene * NB element offsets
__device__ __align__(16) float g_w1f[NP * NKG * NL1 * 2];        // BN-folded, duplicated pairs [p][s][j][2]
__device__ float g_b1f[NP * NL1];
__device__ __align__(16) float g_w2f[NP * NL1 * NL2 * 2];        // [p][t][j][2]
__device__ float g_b2f[NP * NL2];
__device__ __align__(16) float g_w3f[NP * NL2 * NL3 * 2];        // [p][t][j][2]
__device__ float g_b3f[NP * NL3];
__device__ __align__(16) float g_w4f[NP * NL3 * 2];              // [p][t][2]
__device__ __align__(16) float g_scoresT[(size_t)NP * NB];       // [p][b]

// ---- packed f32x2 helpers ---------------------------------------------------
__device__ __forceinline__ unsigned long long fma2(unsigned long long a,
                                                   unsigned long long b,
                                                   unsigned long long c) {
    unsigned long long d;
    asm("fma.rn.f32x2 %0, %1, %2, %3;" : "=l"(d) : "l"(a), "l"(b), "l"(c));
    return d;
}

__device__ __forceinline__ unsigned long long bias_relu2(unsigned long long v, float bias) {
    float a, b;
    asm("mov.b64 {%0, %1}, %2;" : "=f"(a), "=f"(b) : "l"(v));
    a = fmaxf(a + bias, 0.0f);
    b = fmaxf(b + bias, 0.0f);
    unsigned long long r;
    asm("mov.b64 %0, {%1, %2};" : "=l"(r) : "f"(a), "f"(b));
    return r;
}

// ---------------------------------------------------------------------------
// K1: extract the 100 gene indices of each pathway from m1 row p*NL1.
// Deterministic compaction (per-thread count + serial exclusive scan).
// ---------------------------------------------------------------------------
__global__ void extract_genes_kernel(const float* __restrict__ m1) {
    const int p = blockIdx.x;
    const int tid = threadIdx.x;                 // 256 threads
    const float* row = m1 + (size_t)(p * NL1) * NG;

    __shared__ int cnt[257];
    const int CH = (NG + 255) / 256;             // 20
    int start = tid * CH;
    int end = start + CH; if (end > NG) end = NG;
    if (start > NG) start = NG;

    int c = 0;
    for (int g = start; g < end; g++) c += (row[g] != 0.0f);
    cnt[tid + 1] = c;
    __syncthreads();
    if (tid == 0) {
        cnt[0] = 0;
        for (int i = 1; i <= 256; i++) cnt[i] += cnt[i - 1];
    }
    __syncthreads();
    int off = cnt[tid];
    for (int g = start; g < end; g++) {
        if (row[g] != 0.0f) g_geneoff[p * NKG + off++] = g * NB;
    }
}

// ---------------------------------------------------------------------------
// K2: gather w1 along genes, fold eval-mode BatchNorm (scale into W, shift
// into bias) for layers 1..3, store all weights as duplicated f32 pairs.
// ---------------------------------------------------------------------------
__global__ void fold_weights_kernel(
    const float* __restrict__ w1, const float* __restrict__ b1,
    const float* __restrict__ w2, const float* __restrict__ b2,
    const float* __restrict__ w3, const float* __restrict__ b3,
    const float* __restrict__ w4,
    const float* __restrict__ ga1, const float* __restrict__ be1,
    const float* __restrict__ rm1, const float* __restrict__ rv1,
    const float* __restrict__ ga2, const float* __restrict__ be2,
    const float* __restrict__ rm2, const float* __restrict__ rv2,
    const float* __restrict__ ga3, const float* __restrict__ be3,
    const float* __restrict__ rm3, const float* __restrict__ rv3) {
    const int p = blockIdx.x;
    const int tid = threadIdx.x;                 // 256 threads

    __shared__ float s1[NL1], s2[NL2], s3[NL3];
    if (tid < NL1) {
        int u = p * NL1 + tid;
        float s = ga1[u] * rsqrtf(rv1[u] + 1e-5f);
        s1[tid] = s;
        g_b1f[u] = s * (b1[u] - rm1[u]) + be1[u];
    }
    if (tid < NL2) {
        int u = p * NL2 + tid;
        float s = ga2[u] * rsqrtf(rv2[u] + 1e-5f);
        s2[tid] = s;
        g_b2f[u] = s * (b2[u] - rm2[u]) + be2[u];
    }
    if (tid < NL3) {
        int u = p * NL3 + tid;
        float s = ga3[u] * rsqrtf(rv3[u] + 1e-5f);
        s3[tid] = s;
        g_b3f[u] = s * (b3[u] - rm3[u]) + be3[u];
    }
    __syncthreads();

    // layer-1 gather + fold: [p][s][j] duplicated pairs
    for (int i = tid; i < NKG * NL1; i += 256) {
        int s = i / NL1, j = i - s * NL1;
        int gene = g_geneoff[p * NKG + s] >> 13;          // / NB
        float v = w1[(size_t)(p * NL1 + j) * NG + gene] * s1[j];
        size_t o = (((size_t)p * NKG + s) * NL1 + j) * 2;
        g_w1f[o] = v; g_w1f[o + 1] = v;
    }
    // layer-2 block (contiguous columns) : [p][t][j]
    for (int i = tid; i < NL1 * NL2; i += 256) {
        int t = i / NL2, j = i - t * NL2;
        float v = w2[(size_t)(p * NL2 + j) * NH1 + p * NL1 + t] * s2[j];
        size_t o = (((size_t)p * NL1 + t) * NL2 + j) * 2;
        g_w2f[o] = v; g_w2f[o + 1] = v;
    }
    // layer-3 block : [p][t][j]
    if (tid < NL2 * NL3) {
        int t = tid / NL3, j = tid - t * NL3;
        float v = w3[(size_t)(p * NL3 + j) * NH2 + p * NL2 + t] * s3[j];
        size_t o = (((size_t)p * NL2 + t) * NL3 + j) * 2;
        g_w3f[o] = v; g_w3f[o + 1] = v;
    }
    // layer-4 row (no BN) : [p][t]
    if (tid < NL3) {
        float v = w4[(size_t)p * NH3 + p * NL3 + tid];
        g_w4f[(p * NL3 + tid) * 2] = v;
        g_w4f[(p * NL3 + tid) * 2 + 1] = v;
    }
}

// ---------------------------------------------------------------------------
// K3: tiled transpose x[NB,NG] -> g_xT[NG,NB] (coalesced gene rows).
// ---------------------------------------------------------------------------
__global__ void transpose_kernel(const float* __restrict__ x) {
    __shared__ float tile[32][33];
    const int gx = blockIdx.x * 32;              // gene dim
    const int by = blockIdx.y * 32;              // batch dim
    const int tx = threadIdx.x, ty = threadIdx.y;   // (32, 8)

    #pragma unroll
    for (int r = 0; r < 32; r += 8) {
        int b = by + ty + r, g = gx + tx;
        tile[ty + r][tx] = (g < NG) ? x[(size_t)b * NG + g] : 0.0f;
    }
    __syncthreads();
    #pragma unroll
    for (int r = 0; r < 32; r += 8) {
        int g = gx + ty + r, b = by + tx;
        if (g < NG) g_xT[(size_t)g * NB + b] = tile[tx][ty + r];
    }
}

// ---------------------------------------------------------------------------
// Per-batch-pair tail: bias+relu on h1 pair group, then layers 2..4, write
// one float2 of pathway scores. Fully inlined so arrays stay in registers.
// ---------------------------------------------------------------------------
__device__ __forceinline__ void tail_chain(
    unsigned long long* __restrict__ h1,
    const float* __restrict__ s_b1,
    const unsigned long long* __restrict__ s_w2, const float* __restrict__ s_b2,
    const unsigned long long* __restrict__ s_w3, const float* __restrict__ s_b3,
    const unsigned long long* __restrict__ s_w4, float b4v,
    float* __restrict__ dst) {
    #pragma unroll
    for (int j = 0; j < NL1; j++) h1[j] = bias_relu2(h1[j], s_b1[j]);

    unsigned long long h2[NL2];
    #pragma unroll
    for (int j = 0; j < NL2; j++) h2[j] = 0ULL;
    #pragma unroll
    for (int t = 0; t < NL1; t++) {
        #pragma unroll
        for (int j = 0; j < NL2; j++)
            h2[j] = fma2(h1[t], s_w2[t * NL2 + j], h2[j]);
    }
    #pragma unroll
    for (int j = 0; j < NL2; j++) h2[j] = bias_relu2(h2[j], s_b2[j]);

    unsigned long long h3[NL3];
    #pragma unroll
    for (int j = 0; j < NL3; j++) h3[j] = 0ULL;
    #pragma unroll
    for (int t = 0; t < NL2; t++) {
        #pragma unroll
        for (int j = 0; j < NL3; j++)
            h3[j] = fma2(h2[t], s_w3[t * NL3 + j], h3[j]);
    }
    #pragma unroll
    for (int j = 0; j < NL3; j++) h3[j] = bias_relu2(h3[j], s_b3[j]);

    unsigned long long sc = 0ULL;
    #pragma unroll
    for (int t = 0; t < NL3; t++) sc = fma2(h3[t], s_w4[t], sc);

    float sa, sb;
    asm("mov.b64 {%0, %1}, %2;" : "=f"(sa), "=f"(sb) : "l"(sc));
    sa = fmaxf(sa + b4v, 0.0f);
    sb = fmaxf(sb + b4v, 0.0f);
    *reinterpret_cast<float2*>(dst) = make_float2(sa, sb);
}

// ---------------------------------------------------------------------------
// K4: fused pathway chain. Grid (NP pathways fast, 16 batch tiles of 512).
// 128 threads; each thread owns 4 consecutive batch rows (two f32x2 groups).
// Layer-1 inner loop per gene:
//   1 LDG.128 (x quad) + 1 LDS.32 (offset) + 10 LDS.128 (dup weight pairs)
//   + 40 fma.rn.f32x2
// FMA demand (80 SMSP-cyc) >> issue demand (~52) -> fma-pipe bound.
// ---------------------------------------------------------------------------
__global__ void __launch_bounds__(128) pathway_kernel(const float* __restrict__ b4) {
    const int p = blockIdx.x;
    const int tid = threadIdx.x;
    const int b0 = blockIdx.y * 512 + tid * 4;

    __shared__ ulonglong2 s_w1[NKG * NL1 / 2];           // [s][jj] 16 KB
    __shared__ unsigned long long s_w2[NL1 * NL2];       // [t][j]
    __shared__ unsigned long long s_w3[NL2 * NL3];       // [t][j]
    __shared__ unsigned long long s_w4[NL3];
    __shared__ int s_go[NKG];
    __shared__ float s_b1[NL1], s_b2[NL2], s_b3[NL3], s_b4;

    {
        const float4* src1 = reinterpret_cast<const float4*>(g_w1f + (size_t)p * NKG * NL1 * 2);
        float4* dst1 = reinterpret_cast<float4*>(s_w1);
        for (int i = tid; i < NKG * NL1 * 2 / 4; i += 128) dst1[i] = src1[i];

        const float2* src2 = reinterpret_cast<const float2*>(g_w2f + (size_t)p * NL1 * NL2 * 2);
        float2* dst2 = reinterpret_cast<float2*>(s_w2);
        for (int i = tid; i < NL1 * NL2; i += 128) dst2[i] = src2[i];

        const float2* src3 = reinterpret_cast<const float2*>(g_w3f + (size_t)p * NL2 * NL3 * 2);
        float2* dst3 = reinterpret_cast<float2*>(s_w3);
        if (tid < NL2 * NL3) dst3[tid] = src3[tid];

        const float2* src4 = reinterpret_cast<const float2*>(g_w4f + (size_t)p * NL3 * 2);
        float2* dst4 = reinterpret_cast<float2*>(s_w4);
        if (tid < NL3) dst4[tid] = src4[tid];

        if (tid < NKG) s_go[tid] = g_geneoff[p * NKG + tid];
        if (tid < NL1) s_b1[tid] = g_b1f[p * NL1 + tid];
        if (tid < NL2) s_b2[tid] = g_b2f[p * NL2 + tid];
        if (tid < NL3) s_b3[tid] = g_b3f[p * NL3 + tid];
        if (tid == 0)  s_b4 = b4[p];
    }
    __syncthreads();

    // ---- layer 1: 20 units x 100 genes, 4 batch rows per thread ----
    unsigned long long h1a[NL1], h1b[NL1];
    #pragma unroll
    for (int j = 0; j < NL1; j++) { h1a[j] = 0ULL; h1b[j] = 0ULL; }

    const float* xb = g_xT + b0;
    #pragma unroll 2
    for (int s = 0; s < NKG; s++) {
        ulonglong2 xv = *reinterpret_cast<const ulonglong2*>(xb + s_go[s]);
        const ulonglong2* wr = s_w1 + s * (NL1 / 2);
        #pragma unroll
        for (int jj = 0; jj < NL1 / 2; jj++) {
            ulonglong2 w = wr[jj];
            h1a[2 * jj]     = fma2(xv.x, w.x, h1a[2 * jj]);
            h1b[2 * jj]     = fma2(xv.y, w.x, h1b[2 * jj]);
            h1a[2 * jj + 1] = fma2(xv.x, w.y, h1a[2 * jj + 1]);
            h1b[2 * jj + 1] = fma2(xv.y, w.y, h1b[2 * jj + 1]);
        }
    }

    // ---- layers 2..4, one batch-pair group at a time (register peak control)
    float* dst = g_scoresT + (size_t)p * NB + b0;
    tail_chain(h1a, s_b1, s_w2, s_b2, s_w3, s_b3, s_w4, s_b4, dst);
    tail_chain(h1b, s_b1, s_w2, s_b2, s_w3, s_b3, s_w4, s_b4, dst + 2);
}

// ---------------------------------------------------------------------------
// K5: classifier: out[b,l] = sum_k scoresT[k][b] * wc[l,k] + bc[l]
// 4-way K split across lane quads + shfl butterfly reduction -> 1024 warps.
// ---------------------------------------------------------------------------
__global__ void __launch_bounds__(256) classifier_kernel(
    const float* __restrict__ wc, const float* __restrict__ bc,
    float* __restrict__ out) {
    __shared__ float s_wc[NLBL * NP];            // 40 KB
    const int tid = threadIdx.x;

    for (int i = tid; i < NLBL * NP; i += 256) s_wc[i] = wc[i];
    __syncthreads();

    const int gt = blockIdx.x * 256 + tid;
    const int b = gt >> 2;                       // batch row
    const int split = gt & 3;                    // k-quarter
    const int k0 = split * (NP / 4);

    float acc[NLBL];
    #pragma unroll
    for (int l = 0; l < NLBL; l++) acc[l] = 0.0f;

    const float* sp = g_scoresT + b;
    #pragma unroll 2
    for (int k = k0; k < k0 + NP / 4; k++) {
        float sv = sp[(size_t)k * NB];           // 8-lane coalesced per k-row
        #pragma unroll
        for (int l = 0; l < NLBL; l++) acc[l] = fmaf(sv, s_wc[l * NP + k], acc[l]);
    }

    #pragma unroll
    for (int l = 0; l < NLBL; l++) {
        float v = acc[l];
        v += __shfl_xor_sync(0xffffffffu, v, 1);
        v += __shfl_xor_sync(0xffffffffu, v, 2);
        acc[l] = v;
    }

    if (split == 0) {
        float* o = out + (size_t)b * NLBL;
        #pragma unroll
        for (int l = 0; l < NLBL; l++) o[l] = acc[l] + __ldg(bc + l);
    }
}

// ---------------------------------------------------------------------------
// launch
// ---------------------------------------------------------------------------
extern "C" void kernel_launch(void* const* d_in, const int* in_sizes, int n_in,
                              void* d_out, int out_size) {
    const float* x   = (const float*)d_in[0];
    const float* w1  = (const float*)d_in[1];
    const float* b1  = (const float*)d_in[2];
    const float* m1  = (const float*)d_in[3];
    const float* w2  = (const float*)d_in[4];
    const float* b2  = (const float*)d_in[5];
    // m2 = d_in[6]  (unused: block-diagonal by construction)
    const float* w3  = (const float*)d_in[7];
    const float* b3  = (const float*)d_in[8];
    // m3 = d_in[9]
    const float* w4  = (const float*)d_in[10];
    const float* b4  = (const float*)d_in[11];
    // m4 = d_in[12]
    const float* ga1 = (const float*)d_in[13];
    const float* be1 = (const float*)d_in[14];
    const float* rm1 = (const float*)d_in[15];
    const float* rv1 = (const float*)d_in[16];
    const float* ga2 = (const float*)d_in[17];
    const float* be2 = (const float*)d_in[18];
    const float* rm2 = (const float*)d_in[19];
    const float* rv2 = (const float*)d_in[20];
    const float* ga3 = (const float*)d_in[21];
    const float* be3 = (const float*)d_in[22];
    const float* rm3 = (const float*)d_in[23];
    const float* rv3 = (const float*)d_in[24];
    const float* wc  = (const float*)d_in[25];
    const float* bc  = (const float*)d_in[26];
    float* out = (float*)d_out;

    extract_genes_kernel<<<NP, 256>>>(m1);
    fold_weights_kernel<<<NP, 256>>>(w1, b1, w2, b2, w3, b3, w4,
                                     ga1, be1, rm1, rv1,
                                     ga2, be2, rm2, rv2,
                                     ga3, be3, rm3, rv3);
    transpose_kernel<<<dim3((NG + 31) / 32, NB / 32), dim3(32, 8)>>>(x);
    pathway_kernel<<<dim3(NP, NB / 512), 128>>>(b4);
    classifier_kernel<<<NB * 4 / 256, 256>>>(wc, bc, out);
}

// round 4
// speedup vs baseline: 1.4162x; 1.3947x over previous
#include <cuda_runtime.h>

// ---------------------------------------------------------------------------
// EnrichClassifier: block-sparse pathway MLP.
//   dims: x[8192,5000] -> h1[4000] -> h2[2000] -> h3[1000] -> scores[200] -> out[50]
//   Regular structure: every pathway has exactly 100 genes, l1=20, l2=10, l3=5.
//   Layers 2..4 are block-diagonal; only m1 (200 rows of it) must be read.
// ---------------------------------------------------------------------------

#define NG   5000   // genes
#define NB   8192   // batch
#define NP   200    // pathways
#define NKG  100    // genes per pathway
#define NL1  20     // layer-1 units per pathway
#define NL2  10
#define NL3  5
#define NH1  4000
#define NH2  2000
#define NH3  1000
#define NLBL 50

// ---- scratch (device globals: only allowed form of scratch) ----------------
__device__ __align__(16) float g_xT[(size_t)NG * NB];            // 163.84 MB transposed x
__device__ int   g_geneoff[NP * NKG];                            // gene * NB element offsets
__device__ __align__(16) float g_w1f[NP * NKG * NL1 * 2];        // BN-folded, duplicated pairs [p][s][j][2]
__device__ float g_b1f[NP * NL1];
__device__ __align__(16) float g_w2f[NP * NL1 * NL2 * 2];        // [p][t][j][2]
__device__ float g_b2f[NP * NL2];
__device__ __align__(16) float g_w3f[NP * NL2 * NL3 * 2];        // [p][t][j][2]
__device__ float g_b3f[NP * NL3];
__device__ __align__(16) float g_w4f[NP * NL3 * 2];              // [p][t][2]
__device__ __align__(16) float g_scoresT[(size_t)NP * NB];       // [p][b]

// ---- packed f32x2 helpers ---------------------------------------------------
__device__ __forceinline__ unsigned long long fma2(unsigned long long a,
                                                   unsigned long long b,
                                                   unsigned long long c) {
    unsigned long long d;
    asm("fma.rn.f32x2 %0, %1, %2, %3;" : "=l"(d) : "l"(a), "l"(b), "l"(c));
    return d;
}

__device__ __forceinline__ unsigned long long bias_relu2(unsigned long long v, float bias) {
    float a, b;
    asm("mov.b64 {%0, %1}, %2;" : "=f"(a), "=f"(b) : "l"(v));
    a = fmaxf(a + bias, 0.0f);
    b = fmaxf(b + bias, 0.0f);
    unsigned long long r;
    asm("mov.b64 %0, {%1, %2};" : "=l"(r) : "f"(a), "f"(b));
    return r;
}

// ---------------------------------------------------------------------------
// K1: extract the 100 gene indices of each pathway from m1 row p*NL1.
// ---------------------------------------------------------------------------
__global__ void extract_genes_kernel(const float* __restrict__ m1) {
    const int p = blockIdx.x;
    const int tid = threadIdx.x;                 // 256 threads
    const float* row = m1 + (size_t)(p * NL1) * NG;

    __shared__ int cnt[257];
    const int CH = (NG + 255) / 256;             // 20
    int start = tid * CH;
    int end = start + CH; if (end > NG) end = NG;
    if (start > NG) start = NG;

    int c = 0;
    for (int g = start; g < end; g++) c += (row[g] != 0.0f);
    cnt[tid + 1] = c;
    __syncthreads();
    if (tid == 0) {
        cnt[0] = 0;
        for (int i = 1; i <= 256; i++) cnt[i] += cnt[i - 1];
    }
    __syncthreads();
    int off = cnt[tid];
    for (int g = start; g < end; g++) {
        if (row[g] != 0.0f) g_geneoff[p * NKG + off++] = g * NB;
    }
}

// ---------------------------------------------------------------------------
// K2: gather w1 along genes, fold eval-mode BatchNorm into weights/biases,
// store all weights as duplicated f32 pairs.
// ---------------------------------------------------------------------------
__global__ void fold_weights_kernel(
    const float* __restrict__ w1, const float* __restrict__ b1,
    const float* __restrict__ w2, const float* __restrict__ b2,
    const float* __restrict__ w3, const float* __restrict__ b3,
    const float* __restrict__ w4,
    const float* __restrict__ ga1, const float* __restrict__ be1,
    const float* __restrict__ rm1, const float* __restrict__ rv1,
    const float* __restrict__ ga2, const float* __restrict__ be2,
    const float* __restrict__ rm2, const float* __restrict__ rv2,
    const float* __restrict__ ga3, const float* __restrict__ be3,
    const float* __restrict__ rm3, const float* __restrict__ rv3) {
    const int p = blockIdx.x;
    const int tid = threadIdx.x;                 // 256 threads

    __shared__ float s1[NL1], s2[NL2], s3[NL3];
    if (tid < NL1) {
        int u = p * NL1 + tid;
        float s = ga1[u] * rsqrtf(rv1[u] + 1e-5f);
        s1[tid] = s;
        g_b1f[u] = s * (b1[u] - rm1[u]) + be1[u];
    }
    if (tid < NL2) {
        int u = p * NL2 + tid;
        float s = ga2[u] * rsqrtf(rv2[u] + 1e-5f);
        s2[tid] = s;
        g_b2f[u] = s * (b2[u] - rm2[u]) + be2[u];
    }
    if (tid < NL3) {
        int u = p * NL3 + tid;
        float s = ga3[u] * rsqrtf(rv3[u] + 1e-5f);
        s3[tid] = s;
        g_b3f[u] = s * (b3[u] - rm3[u]) + be3[u];
    }
    __syncthreads();

    // layer-1 gather + fold: [p][s][j] duplicated pairs
    for (int i = tid; i < NKG * NL1; i += 256) {
        int s = i / NL1, j = i - s * NL1;
        int gene = g_geneoff[p * NKG + s] >> 13;          // / NB
        float v = w1[(size_t)(p * NL1 + j) * NG + gene] * s1[j];
        size_t o = (((size_t)p * NKG + s) * NL1 + j) * 2;
        g_w1f[o] = v; g_w1f[o + 1] = v;
    }
    // layer-2 block (contiguous columns) : [p][t][j]
    for (int i = tid; i < NL1 * NL2; i += 256) {
        int t = i / NL2, j = i - t * NL2;
        float v = w2[(size_t)(p * NL2 + j) * NH1 + p * NL1 + t] * s2[j];
        size_t o = (((size_t)p * NL1 + t) * NL2 + j) * 2;
        g_w2f[o] = v; g_w2f[o + 1] = v;
    }
    // layer-3 block : [p][t][j]
    if (tid < NL2 * NL3) {
        int t = tid / NL3, j = tid - t * NL3;
        float v = w3[(size_t)(p * NL3 + j) * NH2 + p * NL2 + t] * s3[j];
        size_t o = (((size_t)p * NL2 + t) * NL3 + j) * 2;
        g_w3f[o] = v; g_w3f[o + 1] = v;
    }
    // layer-4 row (no BN) : [p][t]
    if (tid < NL3) {
        float v = w4[(size_t)p * NH3 + p * NL3 + tid];
        g_w4f[(p * NL3 + tid) * 2] = v;
        g_w4f[(p * NL3 + tid) * 2 + 1] = v;
    }
}

// ---------------------------------------------------------------------------
// K3: tiled transpose x[NB,NG] -> g_xT[NG,NB] (coalesced gene rows).
// ---------------------------------------------------------------------------
__global__ void transpose_kernel(const float* __restrict__ x) {
    __shared__ float tile[32][33];
    const int gx = blockIdx.x * 32;              // gene dim
    const int by = blockIdx.y * 32;              // batch dim
    const int tx = threadIdx.x, ty = threadIdx.y;   // (32, 8)

    #pragma unroll
    for (int r = 0; r < 32; r += 8) {
        int b = by + ty + r, g = gx + tx;
        tile[ty + r][tx] = (g < NG) ? x[(size_t)b * NG + g] : 0.0f;
    }
    __syncthreads();
    #pragma unroll
    for (int r = 0; r < 32; r += 8) {
        int g = gx + ty + r, b = by + tx;
        if (g < NG) g_xT[(size_t)g * NB + b] = tile[tx][ty + r];
    }
}

// ---------------------------------------------------------------------------
// Tail: bias+relu on h1, then layers 2..4, write one float2 of scores.
// ---------------------------------------------------------------------------
__device__ __forceinline__ void tail_chain(
    unsigned long long* __restrict__ h1,
    const float* __restrict__ s_b1,
    const unsigned long long* __restrict__ s_w2, const float* __restrict__ s_b2,
    const unsigned long long* __restrict__ s_w3, const float* __restrict__ s_b3,
    const unsigned long long* __restrict__ s_w4, float b4v,
    float* __restrict__ dst) {
    #pragma unroll
    for (int j = 0; j < NL1; j++) h1[j] = bias_relu2(h1[j], s_b1[j]);

    unsigned long long h2[NL2];
    #pragma unroll
    for (int j = 0; j < NL2; j++) h2[j] = 0ULL;
    #pragma unroll
    for (int t = 0; t < NL1; t++) {
        #pragma unroll
        for (int j = 0; j < NL2; j++)
            h2[j] = fma2(h1[t], s_w2[t * NL2 + j], h2[j]);
    }
    #pragma unroll
    for (int j = 0; j < NL2; j++) h2[j] = bias_relu2(h2[j], s_b2[j]);

    unsigned long long h3[NL3];
    #pragma unroll
    for (int j = 0; j < NL3; j++) h3[j] = 0ULL;
    #pragma unroll
    for (int t = 0; t < NL2; t++) {
        #pragma unroll
        for (int j = 0; j < NL3; j++)
            h3[j] = fma2(h2[t], s_w3[t * NL3 + j], h3[j]);
    }
    #pragma unroll
    for (int j = 0; j < NL3; j++) h3[j] = bias_relu2(h3[j], s_b3[j]);

    unsigned long long sc = 0ULL;
    #pragma unroll
    for (int t = 0; t < NL3; t++) sc = fma2(h3[t], s_w4[t], sc);

    float sa, sb;
    asm("mov.b64 {%0, %1}, %2;" : "=f"(sa), "=f"(sb) : "l"(sc));
    sa = fmaxf(sa + b4v, 0.0f);
    sb = fmaxf(sb + b4v, 0.0f);
    *reinterpret_cast<float2*>(dst) = make_float2(sa, sb);
}

// ---------------------------------------------------------------------------
// K4: fused pathway chain. 256 threads, 2 batch rows/thread (f32x2), grid
// (200 pathways, 16 batch tiles of 512). Register budget capped at 128
// (launch_bounds 256,2 -> 2 blocks/SM = 50% occ).
// Layer 1 runs in chunks of PF=10 genes: 10 prefetched LDG.64 (MLP=10 hides
// L2 latency) followed by 10x(10 LDS.128 broadcast + 20 fma.rn.f32x2).
// Per SMSP: fma demand 4 warps x 320cyc > issue 4 x ~250 -> fma-pipe bound.
// ---------------------------------------------------------------------------
#define PF 10

__global__ void __launch_bounds__(256, 2) pathway_kernel(const float* __restrict__ b4) {
    const int p = blockIdx.x;
    const int tid = threadIdx.x;
    const int b0 = blockIdx.y * 512 + tid * 2;

    __shared__ ulonglong2 s_w1[NKG * NL1 / 2];           // [s][jj] 16 KB
    __shared__ unsigned long long s_w2[NL1 * NL2];       // [t][j]
    __shared__ unsigned long long s_w3[NL2 * NL3];       // [t][j]
    __shared__ unsigned long long s_w4[NL3];
    __shared__ int s_go[NKG];
    __shared__ float s_b1[NL1], s_b2[NL2], s_b3[NL3], s_b4;

    {
        const float4* src1 = reinterpret_cast<const float4*>(g_w1f + (size_t)p * NKG * NL1 * 2);
        float4* dst1 = reinterpret_cast<float4*>(s_w1);
        for (int i = tid; i < NKG * NL1 * 2 / 4; i += 256) dst1[i] = src1[i];

        const float2* src2 = reinterpret_cast<const float2*>(g_w2f + (size_t)p * NL1 * NL2 * 2);
        float2* dst2 = reinterpret_cast<float2*>(s_w2);
        if (tid < NL1 * NL2) dst2[tid] = src2[tid];

        const float2* src3 = reinterpret_cast<const float2*>(g_w3f + (size_t)p * NL2 * NL3 * 2);
        float2* dst3 = reinterpret_cast<float2*>(s_w3);
        if (tid < NL2 * NL3) dst3[tid] = src3[tid];

        const float2* src4 = reinterpret_cast<const float2*>(g_w4f + (size_t)p * NL3 * 2);
        float2* dst4 = reinterpret_cast<float2*>(s_w4);
        if (tid < NL3) dst4[tid] = src4[tid];

        if (tid < NKG) s_go[tid] = g_geneoff[p * NKG + tid];
        if (tid < NL1) s_b1[tid] = g_b1f[p * NL1 + tid];
        if (tid < NL2) s_b2[tid] = g_b2f[p * NL2 + tid];
        if (tid < NL3) s_b3[tid] = g_b3f[p * NL3 + tid];
        if (tid == 0)  s_b4 = b4[p];
    }
    __syncthreads();

    // ---- layer 1: 20 units x 100 genes, chunked x prefetch ----
    unsigned long long h1[NL1];
    #pragma unroll
    for (int j = 0; j < NL1; j++) h1[j] = 0ULL;

    const float* xb = g_xT + b0;
    #pragma unroll 1
    for (int c = 0; c < NKG; c += PF) {
        unsigned long long xv[PF];
        #pragma unroll
        for (int u = 0; u < PF; u++)
            xv[u] = *reinterpret_cast<const unsigned long long*>(xb + s_go[c + u]);
        #pragma unroll
        for (int u = 0; u < PF; u++) {
            const ulonglong2* wr = s_w1 + (c + u) * (NL1 / 2);
            #pragma unroll
            for (int jj = 0; jj < NL1 / 2; jj++) {
                ulonglong2 w = wr[jj];
                h1[2 * jj]     = fma2(xv[u], w.x, h1[2 * jj]);
                h1[2 * jj + 1] = fma2(xv[u], w.y, h1[2 * jj + 1]);
            }
        }
    }

    // ---- layers 2..4 ----
    float* dst = g_scoresT + (size_t)p * NB + b0;
    tail_chain(h1, s_b1, s_w2, s_b2, s_w3, s_b3, s_w4, s_b4, dst);
}

// ---------------------------------------------------------------------------
// K5: classifier: out[b,l] = sum_k scoresT[k][b] * wc[l,k] + bc[l]
// 4-way K split across lane quads + shfl butterfly reduction.
// ---------------------------------------------------------------------------
__global__ void __launch_bounds__(256) classifier_kernel(
    const float* __restrict__ wc, const float* __restrict__ bc,
    float* __restrict__ out) {
    __shared__ float s_wc[NLBL * NP];            // 40 KB
    const int tid = threadIdx.x;

    for (int i = tid; i < NLBL * NP; i += 256) s_wc[i] = wc[i];
    __syncthreads();

    const int gt = blockIdx.x * 256 + tid;
    const int b = gt >> 2;                       // batch row
    const int split = gt & 3;                    // k-quarter
    const int k0 = split * (NP / 4);

    float acc[NLBL];
    #pragma unroll
    for (int l = 0; l < NLBL; l++) acc[l] = 0.0f;

    const float* sp = g_scoresT + b;
    #pragma unroll 2
    for (int k = k0; k < k0 + NP / 4; k++) {
        float sv = sp[(size_t)k * NB];           // 8-lane coalesced per k-row
        #pragma unroll
        for (int l = 0; l < NLBL; l++) acc[l] = fmaf(sv, s_wc[l * NP + k], acc[l]);
    }

    #pragma unroll
    for (int l = 0; l < NLBL; l++) {
        float v = acc[l];
        v += __shfl_xor_sync(0xffffffffu, v, 1);
        v += __shfl_xor_sync(0xffffffffu, v, 2);
        acc[l] = v;
    }

    if (split == 0) {
        float* o = out + (size_t)b * NLBL;
        #pragma unroll
        for (int l = 0; l < NLBL; l++) o[l] = acc[l] + __ldg(bc + l);
    }
}

// ---------------------------------------------------------------------------
// launch
// ---------------------------------------------------------------------------
extern "C" void kernel_launch(void* const* d_in, const int* in_sizes, int n_in,
                              void* d_out, int out_size) {
    const float* x   = (const float*)d_in[0];
    const float* w1  = (const float*)d_in[1];
    const float* b1  = (const float*)d_in[2];
    const float* m1  = (const float*)d_in[3];
    const float* w2  = (const float*)d_in[4];
    const float* b2  = (const float*)d_in[5];
    // m2 = d_in[6]  (unused: block-diagonal by construction)
    const float* w3  = (const float*)d_in[7];
    const float* b3  = (const float*)d_in[8];
    // m3 = d_in[9]
    const float* w4  = (const float*)d_in[10];
    const float* b4  = (const float*)d_in[11];
    // m4 = d_in[12]
    const float* ga1 = (const float*)d_in[13];
    const float* be1 = (const float*)d_in[14];
    const float* rm1 = (const float*)d_in[15];
    const float* rv1 = (const float*)d_in[16];
    const float* ga2 = (const float*)d_in[17];
    const float* be2 = (const float*)d_in[18];
    const float* rm2 = (const float*)d_in[19];
    const float* rv2 = (const float*)d_in[20];
    const float* ga3 = (const float*)d_in[21];
    const float* be3 = (const float*)d_in[22];
    const float* rm3 = (const float*)d_in[23];
    const float* rv3 = (const float*)d_in[24];
    const float* wc  = (const float*)d_in[25];
    const float* bc  = (const float*)d_in[26];
    float* out = (float*)d_out;

    extract_genes_kernel<<<NP, 256>>>(m1);
    fold_weights_kernel<<<NP, 256>>>(w1, b1, w2, b2, w3, b3, w4,
                                     ga1, be1, rm1, rv1,
                                     ga2, be2, rm2, rv2,
                                     ga3, be3, rm3, rv3);
    transpose_kernel<<<dim3((NG + 31) / 32, NB / 32), dim3(32, 8)>>>(x);
    pathway_kernel<<<dim3(NP, NB / 512), 256>>>(b4);
    classifier_kernel<<<NB * 4 / 256, 256>>>(wc, bc, out);
}

// round 5
// speedup vs baseline: 1.7722x; 1.2513x over previous
#include <cuda_runtime.h>

// ---------------------------------------------------------------------------
// EnrichClassifier: block-sparse pathway MLP.
//   dims: x[8192,5000] -> h1[4000] -> h2[2000] -> h3[1000] -> scores[200] -> out[50]
//   Regular structure: every pathway has exactly 100 genes, l1=20, l2=10, l3=5.
//   Layers 2..4 are block-diagonal; only m1 (200 rows of it) must be read.
// ---------------------------------------------------------------------------

#define NG   5000   // genes
#define NB   8192   // batch
#define NP   200    // pathways
#define NKG  100    // genes per pathway
#define NL1  20     // layer-1 units per pathway
#define NL2  10
#define NL3  5
#define NH1  4000
#define NH2  2000
#define NH3  1000
#define NLBL 50

// ---- scratch (device globals: only allowed form of scratch) ----------------
__device__ __align__(16) float g_xT[(size_t)NG * NB];            // 163.84 MB transposed x
__device__ int   g_geneoff[NP * NKG];                            // gene * NB element offsets
__device__ __align__(16) float g_w1f[NP * NKG * NL1];            // BN-folded, NON-duplicated [p][s][j]
__device__ float g_b1f[NP * NL1];
__device__ __align__(16) float g_w2f[NP * NL1 * NL2 * 2];        // [p][t][j][2] duplicated pairs
__device__ float g_b2f[NP * NL2];
__device__ __align__(16) float g_w3f[NP * NL2 * NL3 * 2];        // [p][t][j][2]
__device__ float g_b3f[NP * NL3];
__device__ __align__(16) float g_w4f[NP * NL3 * 2];              // [p][t][2]
__device__ __align__(16) float g_scoresT[(size_t)NP * NB];       // [p][b]

// ---- packed f32x2 helpers ---------------------------------------------------
__device__ __forceinline__ unsigned long long fma2(unsigned long long a,
                                                   unsigned long long b,
                                                   unsigned long long c) {
    unsigned long long d;
    asm("fma.rn.f32x2 %0, %1, %2, %3;" : "=l"(d) : "l"(a), "l"(b), "l"(c));
    return d;
}

__device__ __forceinline__ unsigned long long pack2(float lo, float hi) {
    unsigned long long r;
    asm("mov.b64 %0, {%1, %2};" : "=l"(r) : "f"(lo), "f"(hi));
    return r;
}

__device__ __forceinline__ void unpack2(unsigned long long v, float& lo, float& hi) {
    asm("mov.b64 {%0, %1}, %2;" : "=f"(lo), "=f"(hi) : "l"(v));
}

__device__ __forceinline__ unsigned long long bias_relu2(unsigned long long v, float bias) {
    float a, b;
    unpack2(v, a, b);
    a = fmaxf(a + bias, 0.0f);
    b = fmaxf(b + bias, 0.0f);
    return pack2(a, b);
}

// ---------------------------------------------------------------------------
// K1: extract the 100 gene indices of each pathway from m1 row p*NL1.
// ---------------------------------------------------------------------------
__global__ void extract_genes_kernel(const float* __restrict__ m1) {
    const int p = blockIdx.x;
    const int tid = threadIdx.x;                 // 256 threads
    const float* row = m1 + (size_t)(p * NL1) * NG;

    __shared__ int cnt[257];
    const int CH = (NG + 255) / 256;             // 20
    int start = tid * CH;
    int end = start + CH; if (end > NG) end = NG;
    if (start > NG) start = NG;

    int c = 0;
    for (int g = start; g < end; g++) c += (row[g] != 0.0f);
    cnt[tid + 1] = c;
    __syncthreads();
    if (tid == 0) {
        cnt[0] = 0;
        for (int i = 1; i <= 256; i++) cnt[i] += cnt[i - 1];
    }
    __syncthreads();
    int off = cnt[tid];
    for (int g = start; g < end; g++) {
        if (row[g] != 0.0f) g_geneoff[p * NKG + off++] = g * NB;
    }
}

// ---------------------------------------------------------------------------
// K2: gather w1 along genes, fold eval-mode BatchNorm into weights/biases.
// w1 stored plain (unit-packed layer-1); w2/w3/w4 stored duplicated pairs.
// ---------------------------------------------------------------------------
__global__ void fold_weights_kernel(
    const float* __restrict__ w1, const float* __restrict__ b1,
    const float* __restrict__ w2, const float* __restrict__ b2,
    const float* __restrict__ w3, const float* __restrict__ b3,
    const float* __restrict__ w4,
    const float* __restrict__ ga1, const float* __restrict__ be1,
    const float* __restrict__ rm1, const float* __restrict__ rv1,
    const float* __restrict__ ga2, const float* __restrict__ be2,
    const float* __restrict__ rm2, const float* __restrict__ rv2,
    const float* __restrict__ ga3, const float* __restrict__ be3,
    const float* __restrict__ rm3, const float* __restrict__ rv3) {
    const int p = blockIdx.x;
    const int tid = threadIdx.x;                 // 256 threads

    __shared__ float s1[NL1], s2[NL2], s3[NL3];
    if (tid < NL1) {
        int u = p * NL1 + tid;
        float s = ga1[u] * rsqrtf(rv1[u] + 1e-5f);
        s1[tid] = s;
        g_b1f[u] = s * (b1[u] - rm1[u]) + be1[u];
    }
    if (tid < NL2) {
        int u = p * NL2 + tid;
        float s = ga2[u] * rsqrtf(rv2[u] + 1e-5f);
        s2[tid] = s;
        g_b2f[u] = s * (b2[u] - rm2[u]) + be2[u];
    }
    if (tid < NL3) {
        int u = p * NL3 + tid;
        float s = ga3[u] * rsqrtf(rv3[u] + 1e-5f);
        s3[tid] = s;
        g_b3f[u] = s * (b3[u] - rm3[u]) + be3[u];
    }
    __syncthreads();

    // layer-1 gather + fold: [p][s][j] plain floats
    for (int i = tid; i < NKG * NL1; i += 256) {
        int s = i / NL1, j = i - s * NL1;
        int gene = g_geneoff[p * NKG + s] >> 13;          // / NB
        g_w1f[(size_t)p * NKG * NL1 + i] =
            w1[(size_t)(p * NL1 + j) * NG + gene] * s1[j];
    }
    // layer-2 block (contiguous columns) : [p][t][j] duplicated
    for (int i = tid; i < NL1 * NL2; i += 256) {
        int t = i / NL2, j = i - t * NL2;
        float v = w2[(size_t)(p * NL2 + j) * NH1 + p * NL1 + t] * s2[j];
        size_t o = (((size_t)p * NL1 + t) * NL2 + j) * 2;
        g_w2f[o] = v; g_w2f[o + 1] = v;
    }
    // layer-3 block : [p][t][j] duplicated
    if (tid < NL2 * NL3) {
        int t = tid / NL3, j = tid - t * NL3;
        float v = w3[(size_t)(p * NL3 + j) * NH2 + p * NL2 + t] * s3[j];
        size_t o = (((size_t)p * NL2 + t) * NL3 + j) * 2;
        g_w3f[o] = v; g_w3f[o + 1] = v;
    }
    // layer-4 row (no BN) : [p][t] duplicated
    if (tid < NL3) {
        float v = w4[(size_t)p * NH3 + p * NL3 + tid];
        g_w4f[(p * NL3 + tid) * 2] = v;
        g_w4f[(p * NL3 + tid) * 2 + 1] = v;
    }
}

// ---------------------------------------------------------------------------
// K3: tiled transpose x[NB,NG] -> g_xT[NG,NB] (coalesced gene rows).
// ---------------------------------------------------------------------------
__global__ void transpose_kernel(const float* __restrict__ x) {
    __shared__ float tile[32][33];
    const int gx = blockIdx.x * 32;              // gene dim
    const int by = blockIdx.y * 32;              // batch dim
    const int tx = threadIdx.x, ty = threadIdx.y;   // (32, 8)

    #pragma unroll
    for (int r = 0; r < 32; r += 8) {
        int b = by + ty + r, g = gx + tx;
        tile[ty + r][tx] = (g < NG) ? x[(size_t)b * NG + g] : 0.0f;
    }
    __syncthreads();
    #pragma unroll
    for (int r = 0; r < 32; r += 8) {
        int g = gx + ty + r, b = by + tx;
        if (g < NG) g_xT[(size_t)g * NB + b] = tile[tx][ty + r];
    }
}

// ---------------------------------------------------------------------------
// Tail: bias+relu on batch-packed h1, then layers 2..4, write float2 scores.
// ---------------------------------------------------------------------------
__device__ __forceinline__ void tail_chain(
    unsigned long long* __restrict__ h1,
    const float* __restrict__ s_b1,
    const unsigned long long* __restrict__ s_w2, const float* __restrict__ s_b2,
    const unsigned long long* __restrict__ s_w3, const float* __restrict__ s_b3,
    const unsigned long long* __restrict__ s_w4, float b4v,
    float* __restrict__ dst) {
    #pragma unroll
    for (int j = 0; j < NL1; j++) h1[j] = bias_relu2(h1[j], s_b1[j]);

    unsigned long long h2[NL2];
    #pragma unroll
    for (int j = 0; j < NL2; j++) h2[j] = 0ULL;
    #pragma unroll
    for (int t = 0; t < NL1; t++) {
        #pragma unroll
        for (int j = 0; j < NL2; j++)
            h2[j] = fma2(h1[t], s_w2[t * NL2 + j], h2[j]);
    }
    #pragma unroll
    for (int j = 0; j < NL2; j++) h2[j] = bias_relu2(h2[j], s_b2[j]);

    unsigned long long h3[NL3];
    #pragma unroll
    for (int j = 0; j < NL3; j++) h3[j] = 0ULL;
    #pragma unroll
    for (int t = 0; t < NL2; t++) {
        #pragma unroll
        for (int j = 0; j < NL3; j++)
            h3[j] = fma2(h2[t], s_w3[t * NL3 + j], h3[j]);
    }
    #pragma unroll
    for (int j = 0; j < NL3; j++) h3[j] = bias_relu2(h3[j], s_b3[j]);

    unsigned long long sc = 0ULL;
    #pragma unroll
    for (int t = 0; t < NL3; t++) sc = fma2(h3[t], s_w4[t], sc);

    float sa, sb;
    unpack2(sc, sa, sb);
    sa = fmaxf(sa + b4v, 0.0f);
    sb = fmaxf(sb + b4v, 0.0f);
    *reinterpret_cast<float2*>(dst) = make_float2(sa, sb);
}

// ---------------------------------------------------------------------------
// K4: fused pathway chain. 256 threads, 2 batch rows/thread, grid (200, 16).
// Layer 1 is UNIT-PACKED f32x2: weights are natural (w_2k, w_2k+1) pairs in
// smem (non-duplicated, 8KB); x is duplicated per-register (cheap ALU movs).
// Per gene per thread: 1 LDG.64 + 4 MOV + 5 LDS.128 + 20 fma.rn.f32x2.
// Per SMSP (4 warps): fma 160cyc > issue ~128 > smem ~80 -> fma-pipe bound.
// After layer 1, repack unit-pairs -> batch-pairs once and run the tail.
// ---------------------------------------------------------------------------
#define PF 10

__global__ void __launch_bounds__(256, 2) pathway_kernel(const float* __restrict__ b4) {
    const int p = blockIdx.x;
    const int tid = threadIdx.x;
    const int b0 = blockIdx.y * 512 + tid * 2;

    __shared__ ulonglong2 s_w1[NKG * NL1 / 4];           // [s][q]: 4 units per elt, 8 KB
    __shared__ unsigned long long s_w2[NL1 * NL2];       // [t][j] dup pairs
    __shared__ unsigned long long s_w3[NL2 * NL3];       // [t][j]
    __shared__ unsigned long long s_w4[NL3];
    __shared__ int s_go[NKG];
    __shared__ float s_b1[NL1], s_b2[NL2], s_b3[NL3], s_b4;

    {
        const float4* src1 = reinterpret_cast<const float4*>(g_w1f + (size_t)p * NKG * NL1);
        float4* dst1 = reinterpret_cast<float4*>(s_w1);
        for (int i = tid; i < NKG * NL1 / 4; i += 256) dst1[i] = src1[i];

        const float2* src2 = reinterpret_cast<const float2*>(g_w2f + (size_t)p * NL1 * NL2 * 2);
        float2* dst2 = reinterpret_cast<float2*>(s_w2);
        if (tid < NL1 * NL2) dst2[tid] = src2[tid];

        const float2* src3 = reinterpret_cast<const float2*>(g_w3f + (size_t)p * NL2 * NL3 * 2);
        float2* dst3 = reinterpret_cast<float2*>(s_w3);
        if (tid < NL2 * NL3) dst3[tid] = src3[tid];

        const float2* src4 = reinterpret_cast<const float2*>(g_w4f + (size_t)p * NL3 * 2);
        float2* dst4 = reinterpret_cast<float2*>(s_w4);
        if (tid < NL3) dst4[tid] = src4[tid];

        if (tid < NKG) s_go[tid] = g_geneoff[p * NKG + tid];
        if (tid < NL1) s_b1[tid] = g_b1f[p * NL1 + tid];
        if (tid < NL2) s_b2[tid] = g_b2f[p * NL2 + tid];
        if (tid < NL3) s_b3[tid] = g_b3f[p * NL3 + tid];
        if (tid == 0)  s_b4 = b4[p];
    }
    __syncthreads();

    // ---- layer 1: unit-packed accumulators, 2 batch rows ----
    // h1a[k] = {unit2k, unit2k+1} for row0 ; h1b[k] same for row1.
    unsigned long long h1a[NL1 / 2], h1b[NL1 / 2];
    #pragma unroll
    for (int k = 0; k < NL1 / 2; k++) { h1a[k] = 0ULL; h1b[k] = 0ULL; }

    const float* xb = g_xT + b0;
    #pragma unroll 1
    for (int c = 0; c < NKG; c += PF) {
        unsigned long long xv[PF];
        #pragma unroll
        for (int u = 0; u < PF; u++)
            xv[u] = *reinterpret_cast<const unsigned long long*>(xb + s_go[c + u]);
        #pragma unroll
        for (int u = 0; u < PF; u++) {
            float x0, x1;
            unpack2(xv[u], x0, x1);
            unsigned long long xa = pack2(x0, x0);
            unsigned long long xb2 = pack2(x1, x1);
            const ulonglong2* wr = s_w1 + (c + u) * (NL1 / 4);
            #pragma unroll
            for (int q = 0; q < NL1 / 4; q++) {         // 5 LDS.128, 4 units each
                ulonglong2 w = wr[q];
                h1a[2 * q]     = fma2(xa,  w.x, h1a[2 * q]);
                h1b[2 * q]     = fma2(xb2, w.x, h1b[2 * q]);
                h1a[2 * q + 1] = fma2(xa,  w.y, h1a[2 * q + 1]);
                h1b[2 * q + 1] = fma2(xb2, w.y, h1b[2 * q + 1]);
            }
        }
    }

    // ---- repack unit-pairs -> batch-pairs: h1[j] = {row0_j, row1_j} ----
    unsigned long long h1[NL1];
    #pragma unroll
    for (int k = 0; k < NL1 / 2; k++) {
        float a0, a1, c0, c1;
        unpack2(h1a[k], a0, a1);
        unpack2(h1b[k], c0, c1);
        h1[2 * k]     = pack2(a0, c0);
        h1[2 * k + 1] = pack2(a1, c1);
    }

    // ---- layers 2..4 ----
    float* dst = g_scoresT + (size_t)p * NB + b0;
    tail_chain(h1, s_b1, s_w2, s_b2, s_w3, s_b3, s_w4, s_b4, dst);
}

// ---------------------------------------------------------------------------
// K5: classifier: out[b,l] = sum_k scoresT[k][b] * wc[l,k] + bc[l]
// 4-way K split across lane quads + shfl butterfly reduction.
// ---------------------------------------------------------------------------
__global__ void __launch_bounds__(256) classifier_kernel(
    const float* __restrict__ wc, const float* __restrict__ bc,
    float* __restrict__ out) {
    __shared__ float s_wc[NLBL * NP];            // 40 KB
    const int tid = threadIdx.x;

    for (int i = tid; i < NLBL * NP; i += 256) s_wc[i] = wc[i];
    __syncthreads();

    const int gt = blockIdx.x * 256 + tid;
    const int b = gt >> 2;                       // batch row
    const int split = gt & 3;                    // k-quarter
    const int k0 = split * (NP / 4);

    float acc[NLBL];
    #pragma unroll
    for (int l = 0; l < NLBL; l++) acc[l] = 0.0f;

    const float* sp = g_scoresT + b;
    #pragma unroll 2
    for (int k = k0; k < k0 + NP / 4; k++) {
        float sv = sp[(size_t)k * NB];           // 8-lane coalesced per k-row
        #pragma unroll
        for (int l = 0; l < NLBL; l++) acc[l] = fmaf(sv, s_wc[l * NP + k], acc[l]);
    }

    #pragma unroll
    for (int l = 0; l < NLBL; l++) {
        float v = acc[l];
        v += __shfl_xor_sync(0xffffffffu, v, 1);
        v += __shfl_xor_sync(0xffffffffu, v, 2);
        acc[l] = v;
    }

    if (split == 0) {
        float* o = out + (size_t)b * NLBL;
        #pragma unroll
        for (int l = 0; l < NLBL; l++) o[l] = acc[l] + __ldg(bc + l);
    }
}

// ---------------------------------------------------------------------------
// launch
// ---------------------------------------------------------------------------
extern "C" void kernel_launch(void* const* d_in, const int* in_sizes, int n_in,
                              void* d_out, int out_size) {
    const float* x   = (const float*)d_in[0];
    const float* w1  = (const float*)d_in[1];
    const float* b1  = (const float*)d_in[2];
    const float* m1  = (const float*)d_in[3];
    const float* w2  = (const float*)d_in[4];
    const float* b2  = (const float*)d_in[5];
    // m2 = d_in[6]  (unused: block-diagonal by construction)
    const float* w3  = (const float*)d_in[7];
    const float* b3  = (const float*)d_in[8];
    // m3 = d_in[9]
    const float* w4  = (const float*)d_in[10];
    const float* b4  = (const float*)d_in[11];
    // m4 = d_in[12]
    const float* ga1 = (const float*)d_in[13];
    const float* be1 = (const float*)d_in[14];
    const float* rm1 = (const float*)d_in[15];
    const float* rv1 = (const float*)d_in[16];
    const float* ga2 = (const float*)d_in[17];
    const float* be2 = (const float*)d_in[18];
    const float* rm2 = (const float*)d_in[19];
    const float* rv2 = (const float*)d_in[20];
    const float* ga3 = (const float*)d_in[21];
    const float* be3 = (const float*)d_in[22];
    const float* rm3 = (const float*)d_in[23];
    const float* rv3 = (const float*)d_in[24];
    const float* wc  = (const float*)d_in[25];
    const float* bc  = (const float*)d_in[26];
    float* out = (float*)d_out;

    extract_genes_kernel<<<NP, 256>>>(m1);
    fold_weights_kernel<<<NP, 256>>>(w1, b1, w2, b2, w3, b3, w4,
                                     ga1, be1, rm1, rv1,
                                     ga2, be2, rm2, rv2,
                                     ga3, be3, rm3, rv3);
    transpose_kernel<<<dim3((NG + 31) / 32, NB / 32), dim3(32, 8)>>>(x);
    pathway_kernel<<<dim3(NP, NB / 512), 256>>>(b4);
    classifier_kernel<<<NB * 4 / 256, 256>>>(wc, bc, out);
}

// round 6
// speedup vs baseline: 1.8123x; 1.0227x over previous
#include <cuda_runtime.h>

// ---------------------------------------------------------------------------
// EnrichClassifier: block-sparse pathway MLP.
//   dims: x[8192,5000] -> h1[4000] -> h2[2000] -> h3[1000] -> scores[200] -> out[50]
//   Regular structure: every pathway has exactly 100 genes, l1=20, l2=10, l3=5.
//   Layers 2..4 are block-diagonal; only m1 (200 rows of it) must be read.
// ---------------------------------------------------------------------------

#define NG   5000   // genes
#define NB   8192   // batch
#define NP   200    // pathways
#define NKG  100    // genes per pathway
#define NL1  20     // layer-1 units per pathway
#define NL2  10
#define NL3  5
#define NH1  4000
#define NH2  2000
#define NH3  1000
#define NLBL 50

// ---- scratch (device globals: only allowed form of scratch) ----------------
__device__ __align__(16) float g_xT[(size_t)NG * NB];            // 163.84 MB transposed x
__device__ int   g_geneoff[NP * NKG];                            // gene * NB element offsets
__device__ __align__(16) float g_w1f[NP * NKG * NL1];            // BN-folded, NON-duplicated [p][s][j]
__device__ float g_b1f[NP * NL1];
__device__ __align__(16) float g_w2f[NP * NL1 * NL2 * 2];        // [p][t][j][2] duplicated pairs
__device__ float g_b2f[NP * NL2];
__device__ __align__(16) float g_w3f[NP * NL2 * NL3 * 2];        // [p][t][j][2]
__device__ float g_b3f[NP * NL3];
__device__ __align__(16) float g_w4f[NP * NL3 * 2];              // [p][t][2]
__device__ __align__(16) float g_scoresT[(size_t)NP * NB];       // [p][b]

// ---- packed f32x2 helpers ---------------------------------------------------
__device__ __forceinline__ unsigned long long fma2(unsigned long long a,
                                                   unsigned long long b,
                                                   unsigned long long c) {
    unsigned long long d;
    asm("fma.rn.f32x2 %0, %1, %2, %3;" : "=l"(d) : "l"(a), "l"(b), "l"(c));
    return d;
}

__device__ __forceinline__ unsigned long long pack2(float lo, float hi) {
    unsigned long long r;
    asm("mov.b64 %0, {%1, %2};" : "=l"(r) : "f"(lo), "f"(hi));
    return r;
}

__device__ __forceinline__ void unpack2(unsigned long long v, float& lo, float& hi) {
    asm("mov.b64 {%0, %1}, %2;" : "=f"(lo), "=f"(hi) : "l"(v));
}

__device__ __forceinline__ unsigned long long bias_relu2(unsigned long long v, float bias) {
    float a, b;
    unpack2(v, a, b);
    a = fmaxf(a + bias, 0.0f);
    b = fmaxf(b + bias, 0.0f);
    return pack2(a, b);
}

// ---------------------------------------------------------------------------
// K1: extract the 100 gene indices of each pathway from m1 row p*NL1.
// ---------------------------------------------------------------------------
__global__ void extract_genes_kernel(const float* __restrict__ m1) {
    const int p = blockIdx.x;
    const int tid = threadIdx.x;                 // 256 threads
    const float* row = m1 + (size_t)(p * NL1) * NG;

    __shared__ int cnt[257];
    const int CH = (NG + 255) / 256;             // 20
    int start = tid * CH;
    int end = start + CH; if (end > NG) end = NG;
    if (start > NG) start = NG;

    int c = 0;
    for (int g = start; g < end; g++) c += (row[g] != 0.0f);
    cnt[tid + 1] = c;
    __syncthreads();
    if (tid == 0) {
        cnt[0] = 0;
        for (int i = 1; i <= 256; i++) cnt[i] += cnt[i - 1];
    }
    __syncthreads();
    int off = cnt[tid];
    for (int g = start; g < end; g++) {
        if (row[g] != 0.0f) g_geneoff[p * NKG + off++] = g * NB;
    }
}

// ---------------------------------------------------------------------------
// K2: gather w1 along genes, fold eval-mode BatchNorm into weights/biases.
// w1 stored plain (unit-packed layer-1); w2/w3/w4 stored duplicated pairs.
// ---------------------------------------------------------------------------
__global__ void fold_weights_kernel(
    const float* __restrict__ w1, const float* __restrict__ b1,
    const float* __restrict__ w2, const float* __restrict__ b2,
    const float* __restrict__ w3, const float* __restrict__ b3,
    const float* __restrict__ w4,
    const float* __restrict__ ga1, const float* __restrict__ be1,
    const float* __restrict__ rm1, const float* __restrict__ rv1,
    const float* __restrict__ ga2, const float* __restrict__ be2,
    const float* __restrict__ rm2, const float* __restrict__ rv2,
    const float* __restrict__ ga3, const float* __restrict__ be3,
    const float* __restrict__ rm3, const float* __restrict__ rv3) {
    const int p = blockIdx.x;
    const int tid = threadIdx.x;                 // 256 threads

    __shared__ float s1[NL1], s2[NL2], s3[NL3];
    if (tid < NL1) {
        int u = p * NL1 + tid;
        float s = ga1[u] * rsqrtf(rv1[u] + 1e-5f);
        s1[tid] = s;
        g_b1f[u] = s * (b1[u] - rm1[u]) + be1[u];
    }
    if (tid < NL2) {
        int u = p * NL2 + tid;
        float s = ga2[u] * rsqrtf(rv2[u] + 1e-5f);
        s2[tid] = s;
        g_b2f[u] = s * (b2[u] - rm2[u]) + be2[u];
    }
    if (tid < NL3) {
        int u = p * NL3 + tid;
        float s = ga3[u] * rsqrtf(rv3[u] + 1e-5f);
        s3[tid] = s;
        g_b3f[u] = s * (b3[u] - rm3[u]) + be3[u];
    }
    __syncthreads();

    // layer-1 gather + fold: [p][s][j] plain floats
    for (int i = tid; i < NKG * NL1; i += 256) {
        int s = i / NL1, j = i - s * NL1;
        int gene = g_geneoff[p * NKG + s] >> 13;          // / NB
        g_w1f[(size_t)p * NKG * NL1 + i] =
            w1[(size_t)(p * NL1 + j) * NG + gene] * s1[j];
    }
    // layer-2 block (contiguous columns) : [p][t][j] duplicated
    for (int i = tid; i < NL1 * NL2; i += 256) {
        int t = i / NL2, j = i - t * NL2;
        float v = w2[(size_t)(p * NL2 + j) * NH1 + p * NL1 + t] * s2[j];
        size_t o = (((size_t)p * NL1 + t) * NL2 + j) * 2;
        g_w2f[o] = v; g_w2f[o + 1] = v;
    }
    // layer-3 block : [p][t][j] duplicated
    if (tid < NL2 * NL3) {
        int t = tid / NL3, j = tid - t * NL3;
        float v = w3[(size_t)(p * NL3 + j) * NH2 + p * NL2 + t] * s3[j];
        size_t o = (((size_t)p * NL2 + t) * NL3 + j) * 2;
        g_w3f[o] = v; g_w3f[o + 1] = v;
    }
    // layer-4 row (no BN) : [p][t] duplicated
    if (tid < NL3) {
        float v = w4[(size_t)p * NH3 + p * NL3 + tid];
        g_w4f[(p * NL3 + tid) * 2] = v;
        g_w4f[(p * NL3 + tid) * 2 + 1] = v;
    }
}

// ---------------------------------------------------------------------------
// K3: tiled transpose x[NB,NG] -> g_xT[NG,NB] (coalesced gene rows).
// ---------------------------------------------------------------------------
__global__ void transpose_kernel(const float* __restrict__ x) {
    __shared__ float tile[32][33];
    const int gx = blockIdx.x * 32;              // gene dim
    const int by = blockIdx.y * 32;              // batch dim
    const int tx = threadIdx.x, ty = threadIdx.y;   // (32, 8)

    #pragma unroll
    for (int r = 0; r < 32; r += 8) {
        int b = by + ty + r, g = gx + tx;
        tile[ty + r][tx] = (g < NG) ? x[(size_t)b * NG + g] : 0.0f;
    }
    __syncthreads();
    #pragma unroll
    for (int r = 0; r < 32; r += 8) {
        int g = gx + ty + r, b = by + tx;
        if (g < NG) g_xT[(size_t)g * NB + b] = tile[tx][ty + r];
    }
}

// ---------------------------------------------------------------------------
// Tail: bias+relu on batch-packed h1, then layers 2..4, write float2 scores.
// ---------------------------------------------------------------------------
__device__ __forceinline__ void tail_chain(
    unsigned long long* __restrict__ h1,
    const float* __restrict__ s_b1,
    const unsigned long long* __restrict__ s_w2, const float* __restrict__ s_b2,
    const unsigned long long* __restrict__ s_w3, const float* __restrict__ s_b3,
    const unsigned long long* __restrict__ s_w4, float b4v,
    float* __restrict__ dst) {
    #pragma unroll
    for (int j = 0; j < NL1; j++) h1[j] = bias_relu2(h1[j], s_b1[j]);

    unsigned long long h2[NL2];
    #pragma unroll
    for (int j = 0; j < NL2; j++) h2[j] = 0ULL;
    #pragma unroll
    for (int t = 0; t < NL1; t++) {
        #pragma unroll
        for (int j = 0; j < NL2; j++)
            h2[j] = fma2(h1[t], s_w2[t * NL2 + j], h2[j]);
    }
    #pragma unroll
    for (int j = 0; j < NL2; j++) h2[j] = bias_relu2(h2[j], s_b2[j]);

    unsigned long long h3[NL3];
    #pragma unroll
    for (int j = 0; j < NL3; j++) h3[j] = 0ULL;
    #pragma unroll
    for (int t = 0; t < NL2; t++) {
        #pragma unroll
        for (int j = 0; j < NL3; j++)
            h3[j] = fma2(h2[t], s_w3[t * NL3 + j], h3[j]);
    }
    #pragma unroll
    for (int j = 0; j < NL3; j++) h3[j] = bias_relu2(h3[j], s_b3[j]);

    unsigned long long sc = 0ULL;
    #pragma unroll
    for (int t = 0; t < NL3; t++) sc = fma2(h3[t], s_w4[t], sc);

    float sa, sb;
    unpack2(sc, sa, sb);
    sa = fmaxf(sa + b4v, 0.0f);
    sb = fmaxf(sb + b4v, 0.0f);
    *reinterpret_cast<float2*>(dst) = make_float2(sa, sb);
}

// ---------------------------------------------------------------------------
// K4: fused pathway chain. 256 threads, 2 batch rows/thread, grid (200, 16).
// Unit-packed f32x2 layer 1 (weights non-duplicated in smem, 8 KB).
// NEW this round:
//  - software-pipelined gather: double-buffered PF=5 x-prefetch so the ~250cyc
//    L2 gather latency overlaps with the previous chunk's FMA block;
//  - launch_bounds(256,3): reg cap 85 -> 24 warps/SM (37.5% occ), making
//    per-SMSP fma demand (6 warps x 40cyc/gene) exceed issue demand.
// ---------------------------------------------------------------------------
#define PF 5

__global__ void __launch_bounds__(256, 3) pathway_kernel(const float* __restrict__ b4) {
    const int p = blockIdx.x;
    const int tid = threadIdx.x;
    const int b0 = blockIdx.y * 512 + tid * 2;

    __shared__ ulonglong2 s_w1[NKG * NL1 / 4];           // [s][q]: 4 units per elt, 8 KB
    __shared__ unsigned long long s_w2[NL1 * NL2];       // [t][j] dup pairs
    __shared__ unsigned long long s_w3[NL2 * NL3];       // [t][j]
    __shared__ unsigned long long s_w4[NL3];
    __shared__ int s_go[NKG];
    __shared__ float s_b1[NL1], s_b2[NL2], s_b3[NL3], s_b4;

    {
        const float4* src1 = reinterpret_cast<const float4*>(g_w1f + (size_t)p * NKG * NL1);
        float4* dst1 = reinterpret_cast<float4*>(s_w1);
        for (int i = tid; i < NKG * NL1 / 4; i += 256) dst1[i] = src1[i];

        const float2* src2 = reinterpret_cast<const float2*>(g_w2f + (size_t)p * NL1 * NL2 * 2);
        float2* dst2 = reinterpret_cast<float2*>(s_w2);
        if (tid < NL1 * NL2) dst2[tid] = src2[tid];

        const float2* src3 = reinterpret_cast<const float2*>(g_w3f + (size_t)p * NL2 * NL3 * 2);
        float2* dst3 = reinterpret_cast<float2*>(s_w3);
        if (tid < NL2 * NL3) dst3[tid] = src3[tid];

        const float2* src4 = reinterpret_cast<const float2*>(g_w4f + (size_t)p * NL3 * 2);
        float2* dst4 = reinterpret_cast<float2*>(s_w4);
        if (tid < NL3) dst4[tid] = src4[tid];

        if (tid < NKG) s_go[tid] = g_geneoff[p * NKG + tid];
        if (tid < NL1) s_b1[tid] = g_b1f[p * NL1 + tid];
        if (tid < NL2) s_b2[tid] = g_b2f[p * NL2 + tid];
        if (tid < NL3) s_b3[tid] = g_b3f[p * NL3 + tid];
        if (tid == 0)  s_b4 = b4[p];
    }
    __syncthreads();

    // ---- layer 1: unit-packed accumulators, 2 batch rows, pipelined gather
    unsigned long long h1a[NL1 / 2], h1b[NL1 / 2];
    #pragma unroll
    for (int k = 0; k < NL1 / 2; k++) { h1a[k] = 0ULL; h1b[k] = 0ULL; }

    const float* xb = g_xT + b0;
    unsigned long long xv0[PF], xv1[PF];

    // prologue: load genes 0..PF-1
    #pragma unroll
    for (int u = 0; u < PF; u++)
        xv0[u] = *reinterpret_cast<const unsigned long long*>(xb + s_go[u]);

    #pragma unroll 1
    for (int c = 0; c < NKG; c += 2 * PF) {
        // prefetch genes c+PF .. c+2PF-1 into the other buffer
        #pragma unroll
        for (int u = 0; u < PF; u++)
            xv1[u] = *reinterpret_cast<const unsigned long long*>(xb + s_go[c + PF + u]);

        // compute genes c .. c+PF-1 from xv0
        #pragma unroll
        for (int u = 0; u < PF; u++) {
            float x0, x1;
            unpack2(xv0[u], x0, x1);
            unsigned long long xa  = pack2(x0, x0);
            unsigned long long xbb = pack2(x1, x1);
            const ulonglong2* wr = s_w1 + (c + u) * (NL1 / 4);
            #pragma unroll
            for (int q = 0; q < NL1 / 4; q++) {
                ulonglong2 w = wr[q];
                h1a[2 * q]     = fma2(xa,  w.x, h1a[2 * q]);
                h1b[2 * q]     = fma2(xbb, w.x, h1b[2 * q]);
                h1a[2 * q + 1] = fma2(xa,  w.y, h1a[2 * q + 1]);
                h1b[2 * q + 1] = fma2(xbb, w.y, h1b[2 * q + 1]);
            }
        }

        // prefetch genes c+2PF .. c+3PF-1 back into xv0 (skip on last iter)
        if (c + 2 * PF < NKG) {
            #pragma unroll
            for (int u = 0; u < PF; u++)
                xv0[u] = *reinterpret_cast<const unsigned long long*>(xb + s_go[c + 2 * PF + u]);
        }

        // compute genes c+PF .. c+2PF-1 from xv1
        #pragma unroll
        for (int u = 0; u < PF; u++) {
            float x0, x1;
            unpack2(xv1[u], x0, x1);
            unsigned long long xa  = pack2(x0, x0);
            unsigned long long xbb = pack2(x1, x1);
            const ulonglong2* wr = s_w1 + (c + PF + u) * (NL1 / 4);
            #pragma unroll
            for (int q = 0; q < NL1 / 4; q++) {
                ulonglong2 w = wr[q];
                h1a[2 * q]     = fma2(xa,  w.x, h1a[2 * q]);
                h1b[2 * q]     = fma2(xbb, w.x, h1b[2 * q]);
                h1a[2 * q + 1] = fma2(xa,  w.y, h1a[2 * q + 1]);
                h1b[2 * q + 1] = fma2(xbb, w.y, h1b[2 * q + 1]);
            }
        }
    }

    // ---- repack unit-pairs -> batch-pairs: h1[j] = {row0_j, row1_j} ----
    unsigned long long h1[NL1];
    #pragma unroll
    for (int k = 0; k < NL1 / 2; k++) {
        float a0, a1, c0, c1;
        unpack2(h1a[k], a0, a1);
        unpack2(h1b[k], c0, c1);
        h1[2 * k]     = pack2(a0, c0);
        h1[2 * k + 1] = pack2(a1, c1);
    }

    // ---- layers 2..4 ----
    float* dst = g_scoresT + (size_t)p * NB + b0;
    tail_chain(h1, s_b1, s_w2, s_b2, s_w3, s_b3, s_w4, s_b4, dst);
}

// ---------------------------------------------------------------------------
// K5: classifier: out[b,l] = sum_k scoresT[k][b] * wc[l,k] + bc[l]
// 4-way K split across lane quads + shfl butterfly reduction.
// ---------------------------------------------------------------------------
__global__ void __launch_bounds__(256) classifier_kernel(
    const float* __restrict__ wc, const float* __restrict__ bc,
    float* __restrict__ out) {
    __shared__ float s_wc[NLBL * NP];            // 40 KB
    const int tid = threadIdx.x;

    for (int i = tid; i < NLBL * NP; i += 256) s_wc[i] = wc[i];
    __syncthreads();

    const int gt = blockIdx.x * 256 + tid;
    const int b = gt >> 2;                       // batch row
    const int split = gt & 3;                    // k-quarter
    const int k0 = split * (NP / 4);

    float acc[NLBL];
    #pragma unroll
    for (int l = 0; l < NLBL; l++) acc[l] = 0.0f;

    const float* sp = g_scoresT + b;
    #pragma unroll 2
    for (int k = k0; k < k0 + NP / 4; k++) {
        float sv = sp[(size_t)k * NB];           // 8-lane coalesced per k-row
        #pragma unroll
        for (int l = 0; l < NLBL; l++) acc[l] = fmaf(sv, s_wc[l * NP + k], acc[l]);
    }

    #pragma unroll
    for (int l = 0; l < NLBL; l++) {
        float v = acc[l];
        v += __shfl_xor_sync(0xffffffffu, v, 1);
        v += __shfl_xor_sync(0xffffffffu, v, 2);
        acc[l] = v;
    }

    if (split == 0) {
        float* o = out + (size_t)b * NLBL;
        #pragma unroll
        for (int l = 0; l < NLBL; l++) o[l] = acc[l] + __ldg(bc + l);
    }
}

// ---------------------------------------------------------------------------
// launch
// ---------------------------------------------------------------------------
extern "C" void kernel_launch(void* const* d_in, const int* in_sizes, int n_in,
                              void* d_out, int out_size) {
    const float* x   = (const float*)d_in[0];
    const float* w1  = (const float*)d_in[1];
    const float* b1  = (const float*)d_in[2];
    const float* m1  = (const float*)d_in[3];
    const float* w2  = (const float*)d_in[4];
    const float* b2  = (const float*)d_in[5];
    // m2 = d_in[6]  (unused: block-diagonal by construction)
    const float* w3  = (const float*)d_in[7];
    const float* b3  = (const float*)d_in[8];
    // m3 = d_in[9]
    const float* w4  = (const float*)d_in[10];
    const float* b4  = (const float*)d_in[11];
    // m4 = d_in[12]
    const float* ga1 = (const float*)d_in[13];
    const float* be1 = (const float*)d_in[14];
    const float* rm1 = (const float*)d_in[15];
    const float* rv1 = (const float*)d_in[16];
    const float* ga2 = (const float*)d_in[17];
    const float* be2 = (const float*)d_in[18];
    const float* rm2 = (const float*)d_in[19];
    const float* rv2 = (const float*)d_in[20];
    const float* ga3 = (const float*)d_in[21];
    const float* be3 = (const float*)d_in[22];
    const float* rm3 = (const float*)d_in[23];
    const float* rv3 = (const float*)d_in[24];
    const float* wc  = (const float*)d_in[25];
    const float* bc  = (const float*)d_in[26];
    float* out = (float*)d_out;

    extract_genes_kernel<<<NP, 256>>>(m1);
    fold_weights_kernel<<<NP, 256>>>(w1, b1, w2, b2, w3, b3, w4,
                                     ga1, be1, rm1, rv1,
                                     ga2, be2, rm2, rv2,
                                     ga3, be3, rm3, rv3);
    transpose_kernel<<<dim3((NG + 31) / 32, NB / 32), dim3(32, 8)>>>(x);
    pathway_kernel<<<dim3(NP, NB / 512), 256>>>(b4);
    classifier_kernel<<<NB * 4 / 256, 256>>>(wc, bc, out);
}